// round 6
// baseline (speedup 1.0000x reference)
#include <cuda_runtime.h>
#include <cstdint>

#define LRELU(v) ((v) > 0.0f ? (v) : 0.01f * (v))
using ull = unsigned long long;

static constexpr int Bb   = 512;
static constexpr int Nn   = 64;
static constexpr int Hh   = 4;
static constexpr int FOUT = 16;

// Scratch for inter-stage activations (x1, x2: [B, N, 128])
__device__ float g_x1[(size_t)Bb * Nn * 128];
__device__ float g_x2[(size_t)Bb * Nn * 128];

// ---------------------------------------------------------------------------
// Packed fp32x2 helpers (Blackwell FFMA2 — only reachable via PTX)
// ---------------------------------------------------------------------------
__device__ __forceinline__ ull pack2(float a, float b) {
    ull r;
    asm("mov.b64 %0, {%1, %2};" : "=l"(r) : "f"(a), "f"(b));
    return r;
}
__device__ __forceinline__ void unpack2(ull v, float& a, float& b) {
    asm("mov.b64 {%0, %1}, %2;" : "=f"(a), "=f"(b) : "l"(v));
}
__device__ __forceinline__ ull fma2(ull a, ull b, ull c) {
    ull d;
    asm("fma.rn.f32x2 %0, %1, %2, %3;" : "=l"(d) : "l"(a), "l"(b), "l"(c));
    return d;
}

// ---------------------------------------------------------------------------
// cp.async helpers
// ---------------------------------------------------------------------------
__device__ __forceinline__ uint32_t s2u(const void* p) {
    return (uint32_t)__cvta_generic_to_shared(p);
}
__device__ __forceinline__ void cp4(uint32_t dst, const float* src) {
    asm volatile("cp.async.ca.shared.global [%0], [%1], 4;" :: "r"(dst), "l"(src));
}
__device__ __forceinline__ void cp_commit() {
    asm volatile("cp.async.commit_group;" ::: "memory");
}
template<int N>
__device__ __forceinline__ void cp_wait() {
    asm volatile("cp.async.wait_group %0;" :: "n"(N) : "memory");
}

// ---------------------------------------------------------------------------
// Register-blocked packed GEMM: C[64][NC] = A(smem)[64][K] * W(gmem)[NC][K]^T + b
// 512 threads: tx = tid&15 (16), ty = tid>>4 (32); micro-tile 2 rows x CW cols.
// W k-tiles staged transposed [kk][n] (stride 132) via double-buffered cp.async,
// so B-loads are contiguous LDS.128 reinterpreted as f32x2 pairs.
// ---------------------------------------------------------------------------
template<int CW>
__device__ __forceinline__ void gemm(
    const float* __restrict__ sA, int lda, int Kdim,
    const float* __restrict__ gW, const float* __restrict__ gBias,
    float* __restrict__ sWt,              // 2 buffers of 32*132 floats
    float* __restrict__ sOut, int ldo, bool outT, bool relu,
    int tx, int ty, int tid)
{
    constexpr int NC    = CW * 16;
    constexpr int NPAIR = CW / 2;
    ull acc[2][NPAIR];
#pragma unroll
    for (int i = 0; i < 2; ++i)
#pragma unroll
        for (int p = 0; p < NPAIR; ++p) acc[i][p] = 0ull;

    const int kk = tid & 31;
    const int n0 = tid >> 5;               // 0..15
    const int ntiles = Kdim / 32;

    // stage tile t into buffer buf (transposed [kk][n])
    auto stage = [&](int t, int buf) {
        float* dst = sWt + buf * (32 * 132) + kk * 132;
        const float* src = gW + (size_t)t * 32 + kk;
#pragma unroll
        for (int n = n0; n < NC; n += 16)
            cp4(s2u(dst + n), src + (size_t)n * Kdim);
        cp_commit();
    };

    stage(0, 0);
    for (int t = 0; t < ntiles; ++t) {
        if (t + 1 < ntiles) { stage(t + 1, (t + 1) & 1); cp_wait<1>(); }
        else                { cp_wait<0>(); }
        __syncthreads();                   // tile t ready; fences prior phase smem
        const float* w   = sWt + (t & 1) * (32 * 132);
        const float* a0r = sA + (2 * ty)     * lda + t * 32;
        const float* a1r = sA + (2 * ty + 1) * lda + t * 32;
#pragma unroll
        for (int k4 = 0; k4 < 8; ++k4) {
            float4 a0 = *(const float4*)(a0r + 4 * k4);
            float4 a1 = *(const float4*)(a1r + 4 * k4);
#pragma unroll
            for (int q = 0; q < 4; ++q) {
                float av0 = (&a0.x)[q], av1 = (&a1.x)[q];
                ull ap0 = pack2(av0, av0);
                ull ap1 = pack2(av1, av1);
                const ull* bp = (const ull*)(w + (4 * k4 + q) * 132 + CW * tx);
#pragma unroll
                for (int p = 0; p < NPAIR; ++p) {
                    ull bb = bp[p];
                    acc[0][p] = fma2(ap0, bb, acc[0][p]);
                    acc[1][p] = fma2(ap1, bb, acc[1][p]);
                }
            }
        }
        __syncthreads();                   // safe to overwrite buffer t&1
    }

    // epilogue
#pragma unroll
    for (int p = 0; p < NPAIR; ++p) {
        int col = CW * tx + 2 * p;
        float b0 = gBias[col], b1 = gBias[col + 1];
#pragma unroll
        for (int i = 0; i < 2; ++i) {
            float v0, v1; unpack2(acc[i][p], v0, v1);
            v0 += b0; v1 += b1;
            if (relu) { v0 = LRELU(v0); v1 = LRELU(v1); }
            int row = 2 * ty + i;
            if (outT) { sOut[col * ldo + row] = v0; sOut[(col + 1) * ldo + row] = v1; }
            else      { sOut[row * ldo + col] = v0; sOut[row * ldo + col + 1]   = v1; }
        }
    }
}

// ---------------------------------------------------------------------------
// Fused attention block: one CTA (512 threads) per (head h, batch b).
// ---------------------------------------------------------------------------
template<int IN_DIM>
__global__ void __launch_bounds__(512, 1)
attn_kernel(const float* __restrict__ x,
            const float* __restrict__ Ew, const float* __restrict__ Eb,
            const float* __restrict__ Kw, const float* __restrict__ Kb,
            const float* __restrict__ Qw, const float* __restrict__ Qb,
            const float* __restrict__ Vw, const float* __restrict__ Vb,
            float* __restrict__ w_out, float* __restrict__ x_out)
{
    extern __shared__ float smem[];
    const int h = blockIdx.x, b = blockIdx.y;
    const int tid = threadIdx.x, tx = tid & 15, ty = tid >> 4;

    float* s_x  = smem;                     // 64*IN_DIM (reused as s_w later)
    float* s_se = s_x  + 64 * IN_DIM;       // 64*128
    float* s_kT = s_se + 64 * 128;          // 128*68  (k^T: [e][m])
    float* s_q  = s_kT + 128 * 68;          // 64*128
    float* s_v  = s_q  + 64 * 128;          // 64*32
    float* s_wt = s_v  + 64 * 32;           // 2 * 32*132 staging
    float* s_w  = s_x;                      // 64*64 overlay

    // Load input tile x[b] (coalesced float4); fenced by gemm's first barrier.
    const float* gx = x + (size_t)b * 64 * IN_DIM;
    for (int i = 4 * tid; i < 64 * IN_DIM; i += 2048)
        *(float4*)&s_x[i] = *(const float4*)&gx[i];

    // Phase 1: se = lrelu(x @ Ew^T + Eb)
    gemm<8>(s_x, IN_DIM, IN_DIM,
            Ew + (size_t)h * 128 * IN_DIM, Eb + h * 128,
            s_wt, s_se, 128, false, true, tx, ty, tid);
    // Phase 2: k^T, q, v
    gemm<8>(s_se, 128, 128, Kw + (size_t)h * 128 * 128, Kb + h * 128,
            s_wt, s_kT, 68, true, false, tx, ty, tid);
    gemm<8>(s_se, 128, 128, Qw + (size_t)h * 128 * 128, Qb + h * 128,
            s_wt, s_q, 128, false, false, tx, ty, tid);
    gemm<2>(s_se, 128, 128, Vw + (size_t)h * 32 * 128, Vb + h * 32,
            s_wt, s_v, 32, false, true, tx, ty, tid);
    __syncthreads();

    // Phase 3: scores (64x64, K=128) + row softmax. micro-tile 2x4 (2 pairs).
    ull sacc[2][2] = {{0ull, 0ull}, {0ull, 0ull}};
#pragma unroll 8
    for (int k4 = 0; k4 < 32; ++k4) {
        float4 a0 = *(const float4*)&s_q[(2 * ty)     * 128 + 4 * k4];
        float4 a1 = *(const float4*)&s_q[(2 * ty + 1) * 128 + 4 * k4];
#pragma unroll
        for (int q = 0; q < 4; ++q) {
            float av0 = (&a0.x)[q], av1 = (&a1.x)[q];
            ull ap0 = pack2(av0, av0);
            ull ap1 = pack2(av1, av1);
            const ull* bp = (const ull*)&s_kT[(4 * k4 + q) * 68 + 4 * tx];
            ull b0 = bp[0], b1 = bp[1];
            sacc[0][0] = fma2(ap0, b0, sacc[0][0]);
            sacc[0][1] = fma2(ap0, b1, sacc[0][1]);
            sacc[1][0] = fma2(ap1, b0, sacc[1][0]);
            sacc[1][1] = fma2(ap1, b1, sacc[1][1]);
        }
    }
    const float SCALE = 0.08838834764831845f;  // 1/sqrt(128)
    float* wg = w_out + (((size_t)h * Bb + b) * 64) * 64;
#pragma unroll
    for (int i = 0; i < 2; ++i) {
        float sc[4];
        unpack2(sacc[i][0], sc[0], sc[1]);
        unpack2(sacc[i][1], sc[2], sc[3]);
        float m = -3.0e38f;
#pragma unroll
        for (int j = 0; j < 4; ++j) { sc[j] *= SCALE; m = fmaxf(m, sc[j]); }
#pragma unroll
        for (int off = 1; off < 16; off <<= 1)
            m = fmaxf(m, __shfl_xor_sync(0xffffffffu, m, off));
        float s = 0.0f;
#pragma unroll
        for (int j = 0; j < 4; ++j) { sc[j] = __expf(sc[j] - m); s += sc[j]; }
#pragma unroll
        for (int off = 1; off < 16; off <<= 1)
            s += __shfl_xor_sync(0xffffffffu, s, off);
        float inv = 1.0f / s;
        float4 wv = make_float4(sc[0] * inv, sc[1] * inv, sc[2] * inv, sc[3] * inv);
        int row = 2 * ty + i;
        *(float4*)&s_w[row * 64 + 4 * tx] = wv;
        *(float4*)&wg[(size_t)row * 64 + 4 * tx] = wv;
    }
    __syncthreads();

    // Phase 4: att = w @ v (64x32, K=64). micro-tile 2x2 (1 pair).
    ull aacc[2] = {0ull, 0ull};
#pragma unroll 8
    for (int k4 = 0; k4 < 16; ++k4) {
        float4 a0 = *(const float4*)&s_w[(2 * ty)     * 64 + 4 * k4];
        float4 a1 = *(const float4*)&s_w[(2 * ty + 1) * 64 + 4 * k4];
#pragma unroll
        for (int q = 0; q < 4; ++q) {
            float av0 = (&a0.x)[q], av1 = (&a1.x)[q];
            ull bb = *(const ull*)&s_v[(4 * k4 + q) * 32 + 2 * tx];
            aacc[0] = fma2(pack2(av0, av0), bb, aacc[0]);
            aacc[1] = fma2(pack2(av1, av1), bb, aacc[1]);
        }
    }
#pragma unroll
    for (int i = 0; i < 2; ++i) {
        float v0, v1; unpack2(aacc[i], v0, v1);
        int row = 2 * ty + i;
        *(float2*)&x_out[((size_t)b * 64 + row) * 128 + h * 32 + 2 * tx] =
            make_float2(v0, v1);
    }
}

// ---------------------------------------------------------------------------
// Final MLP + softmax policy head (unchanged — ~2% of runtime).
// ---------------------------------------------------------------------------
__global__ void __launch_bounds__(256)
mlp_kernel(const float* __restrict__ x,
           const float* __restrict__ F1w, const float* __restrict__ F1b,
           const float* __restrict__ F2w, const float* __restrict__ F2b,
           float* __restrict__ out)
{
    __shared__ float sF1[128 * 65];
    __shared__ float sF2[16 * 64];
    __shared__ float sB1[64];
    __shared__ float sB2[16];
    __shared__ float sx[8][2][128];

    const int tid = threadIdx.x, lane = tid & 31, warp = tid >> 5;

    for (int idx = tid; idx < 64 * 128; idx += 256) {
        int o = idx >> 7, d = idx & 127;
        sF1[d * 65 + o] = F1w[idx];
    }
    for (int idx = tid; idx < 16 * 64; idx += 256) sF2[idx] = F2w[idx];
    if (tid < 64) sB1[tid] = F1b[tid];
    if (tid < 16) sB2[tid] = F2b[tid];
    __syncthreads();

    const int NGRP = (Bb * Nn) / 2;
    for (int g = blockIdx.x * 8 + warp; g < NGRP; g += gridDim.x * 8) {
        int row0 = g * 2;
#pragma unroll
        for (int r = 0; r < 2; ++r)
            *(float4*)&sx[warp][r][lane * 4] =
                *(const float4*)&x[(size_t)(row0 + r) * 128 + lane * 4];
        __syncwarp();

        float h0[2], h1[2];
        h0[0] = h0[1] = sB1[lane];
        h1[0] = h1[1] = sB1[lane + 32];
#pragma unroll 8
        for (int d = 0; d < 128; ++d) {
            float w0 = sF1[d * 65 + lane];
            float w1 = sF1[d * 65 + 32 + lane];
#pragma unroll
            for (int r = 0; r < 2; ++r) {
                float xv = sx[warp][r][d];
                h0[r] = fmaf(xv, w0, h0[r]);
                h1[r] = fmaf(xv, w1, h1[r]);
            }
        }
#pragma unroll
        for (int r = 0; r < 2; ++r) { h0[r] = LRELU(h0[r]); h1[r] = LRELU(h1[r]); }

#pragma unroll
        for (int r = 0; r < 2; ++r) {
            float p[16];
#pragma unroll
            for (int j = 0; j < 16; ++j) {
                float t = fmaf(h0[r], sF2[j * 64 + lane],
                               h1[r] * sF2[j * 64 + 32 + lane]);
#pragma unroll
                for (int off = 16; off > 0; off >>= 1)
                    t += __shfl_xor_sync(0xffffffffu, t, off);
                p[j] = t + sB2[j];
            }
            float m = p[0];
#pragma unroll
            for (int j = 1; j < 16; ++j) m = fmaxf(m, p[j]);
            float s = 0.0f;
#pragma unroll
            for (int j = 0; j < 16; ++j) { p[j] = __expf(p[j] - m); s += p[j]; }
            float inv = 1.0f / s;
            float mine = 0.0f;
#pragma unroll
            for (int j = 0; j < 16; ++j) mine = (lane == j) ? p[j] * inv : mine;
            if (lane < 16) out[(size_t)(row0 + r) * 16 + lane] = mine;
        }
        __syncwarp();
    }
}

// ---------------------------------------------------------------------------
extern "C" void kernel_launch(void* const* d_in, const int* in_sizes, int n_in,
                              void* d_out, int out_size)
{
    const float* states = (const float*)d_in[0];
    const float* E1w = (const float*)d_in[1];  const float* E1b = (const float*)d_in[2];
    const float* K1w = (const float*)d_in[3];  const float* K1b = (const float*)d_in[4];
    const float* Q1w = (const float*)d_in[5];  const float* Q1b = (const float*)d_in[6];
    const float* V1w = (const float*)d_in[7];  const float* V1b = (const float*)d_in[8];
    const float* E2w = (const float*)d_in[9];  const float* E2b = (const float*)d_in[10];
    const float* K2w = (const float*)d_in[11]; const float* K2b = (const float*)d_in[12];
    const float* Q2w = (const float*)d_in[13]; const float* Q2b = (const float*)d_in[14];
    const float* V2w = (const float*)d_in[15]; const float* V2b = (const float*)d_in[16];
    const float* F1w = (const float*)d_in[17]; const float* F1b = (const float*)d_in[18];
    const float* F2w = (const float*)d_in[19]; const float* F2b = (const float*)d_in[20];

    float* out    = (float*)d_out;
    float* policy = out;                                      // [512,64,16]
    float* w1     = out + (size_t)Bb * Nn * FOUT;             // [4,512,64,64]
    float* w2     = w1 + (size_t)Hh * Bb * Nn * Nn;           // [4,512,64,64]

    float* x1p = nullptr; float* x2p = nullptr;
    cudaGetSymbolAddress((void**)&x1p, g_x1);
    cudaGetSymbolAddress((void**)&x2p, g_x2);

    const int SMEM1 = (64*256 + 64*128 + 128*68 + 64*128 + 64*32 + 2*32*132) * 4;
    const int SMEM2 = (64*128 + 64*128 + 128*68 + 64*128 + 64*32 + 2*32*132) * 4;
    cudaFuncSetAttribute(attn_kernel<256>, cudaFuncAttributeMaxDynamicSharedMemorySize, SMEM1);
    cudaFuncSetAttribute(attn_kernel<128>, cudaFuncAttributeMaxDynamicSharedMemorySize, SMEM2);

    dim3 grid(Hh, Bb);
    attn_kernel<256><<<grid, 512, SMEM1>>>(states, E1w, E1b, K1w, K1b,
                                           Q1w, Q1b, V1w, V1b, w1, x1p);
    attn_kernel<128><<<grid, 512, SMEM2>>>(x1p, E2w, E2b, K2w, K2b,
                                           Q2w, Q2b, V2w, V2b, w2, x2p);
    mlp_kernel<<<512, 256>>>(x2p, F1w, F1b, F2w, F2b, policy);
}

// round 7
// speedup vs baseline: 1.0012x; 1.0012x over previous
#include <cuda_runtime.h>
#include <cstdint>

#define LRELU(v) ((v) > 0.0f ? (v) : 0.01f * (v))
using ull = unsigned long long;

static constexpr int Bb   = 512;
static constexpr int Nn   = 64;
static constexpr int Hh   = 4;
static constexpr int FOUT = 16;

// Scratch for inter-stage activations (x1, x2: [B, N, 128])
__device__ float g_x1[(size_t)Bb * Nn * 128];
__device__ float g_x2[(size_t)Bb * Nn * 128];

// ---------------------------------------------------------------------------
// Packed fp32x2 helpers (Blackwell FFMA2 — only reachable via PTX)
// ---------------------------------------------------------------------------
__device__ __forceinline__ ull pack2(float a, float b) {
    ull r;
    asm("mov.b64 %0, {%1, %2};" : "=l"(r) : "f"(a), "f"(b));
    return r;
}
__device__ __forceinline__ void unpack2(ull v, float& a, float& b) {
    asm("mov.b64 {%0, %1}, %2;" : "=f"(a), "=f"(b) : "l"(v));
}
__device__ __forceinline__ ull fma2(ull a, ull b, ull c) {
    ull d;
    asm("fma.rn.f32x2 %0, %1, %2, %3;" : "=l"(d) : "l"(a), "l"(b), "l"(c));
    return d;
}

// ---------------------------------------------------------------------------
// cp.async helpers
// ---------------------------------------------------------------------------
__device__ __forceinline__ uint32_t s2u(const void* p) {
    return (uint32_t)__cvta_generic_to_shared(p);
}
__device__ __forceinline__ void cp4(uint32_t dst, const float* src) {
    asm volatile("cp.async.ca.shared.global [%0], [%1], 4;" :: "r"(dst), "l"(src));
}
__device__ __forceinline__ void cp_commit() {
    asm volatile("cp.async.commit_group;" ::: "memory");
}
template<int N>
__device__ __forceinline__ void cp_wait() {
    asm volatile("cp.async.wait_group %0;" :: "n"(N) : "memory");
}

// ---------------------------------------------------------------------------
// Register-blocked packed GEMM: C[64][NC] = A(smem)[64][K] * W(gmem)[NC][K]^T + b
// 512 threads: tx = tid&15 (16), ty = tid>>4 (32); micro-tile 2 rows x CW cols.
// W k-tiles staged transposed [kk][n] (stride 132) via double-buffered cp.async,
// so B-loads are contiguous LDS.128 reinterpreted as f32x2 pairs.
// ---------------------------------------------------------------------------
template<int CW>
__device__ __forceinline__ void gemm(
    const float* __restrict__ sA, int lda, int Kdim,
    const float* __restrict__ gW, const float* __restrict__ gBias,
    float* __restrict__ sWt,              // 2 buffers of 32*132 floats
    float* __restrict__ sOut, int ldo, bool outT, bool relu,
    int tx, int ty, int tid)
{
    constexpr int NC    = CW * 16;
    constexpr int NPAIR = CW / 2;
    ull acc[2][NPAIR];
#pragma unroll
    for (int i = 0; i < 2; ++i)
#pragma unroll
        for (int p = 0; p < NPAIR; ++p) acc[i][p] = 0ull;

    const int kk = tid & 31;
    const int n0 = tid >> 5;               // 0..15
    const int ntiles = Kdim / 32;

    // stage tile t into buffer buf (transposed [kk][n])
    auto stage = [&](int t, int buf) {
        float* dst = sWt + buf * (32 * 132) + kk * 132;
        const float* src = gW + (size_t)t * 32 + kk;
#pragma unroll
        for (int n = n0; n < NC; n += 16)
            cp4(s2u(dst + n), src + (size_t)n * Kdim);
        cp_commit();
    };

    stage(0, 0);
    for (int t = 0; t < ntiles; ++t) {
        if (t + 1 < ntiles) { stage(t + 1, (t + 1) & 1); cp_wait<1>(); }
        else                { cp_wait<0>(); }
        __syncthreads();                   // tile t ready; fences prior phase smem
        const float* w   = sWt + (t & 1) * (32 * 132);
        const float* a0r = sA + (2 * ty)     * lda + t * 32;
        const float* a1r = sA + (2 * ty + 1) * lda + t * 32;
#pragma unroll
        for (int k4 = 0; k4 < 8; ++k4) {
            float4 a0 = *(const float4*)(a0r + 4 * k4);
            float4 a1 = *(const float4*)(a1r + 4 * k4);
#pragma unroll
            for (int q = 0; q < 4; ++q) {
                float av0 = (&a0.x)[q], av1 = (&a1.x)[q];
                ull ap0 = pack2(av0, av0);
                ull ap1 = pack2(av1, av1);
                const ull* bp = (const ull*)(w + (4 * k4 + q) * 132 + CW * tx);
#pragma unroll
                for (int p = 0; p < NPAIR; ++p) {
                    ull bb = bp[p];
                    acc[0][p] = fma2(ap0, bb, acc[0][p]);
                    acc[1][p] = fma2(ap1, bb, acc[1][p]);
                }
            }
        }
        __syncthreads();                   // safe to overwrite buffer t&1
    }

    // epilogue
#pragma unroll
    for (int p = 0; p < NPAIR; ++p) {
        int col = CW * tx + 2 * p;
        float b0 = gBias[col], b1 = gBias[col + 1];
#pragma unroll
        for (int i = 0; i < 2; ++i) {
            float v0, v1; unpack2(acc[i][p], v0, v1);
            v0 += b0; v1 += b1;
            if (relu) { v0 = LRELU(v0); v1 = LRELU(v1); }
            int row = 2 * ty + i;
            if (outT) { sOut[col * ldo + row] = v0; sOut[(col + 1) * ldo + row] = v1; }
            else      { sOut[row * ldo + col] = v0; sOut[row * ldo + col + 1]   = v1; }
        }
    }
}

// ---------------------------------------------------------------------------
// Fused attention block: one CTA (512 threads) per (head h, batch b).
// ---------------------------------------------------------------------------
template<int IN_DIM>
__global__ void __launch_bounds__(512, 1)
attn_kernel(const float* __restrict__ x,
            const float* __restrict__ Ew, const float* __restrict__ Eb,
            const float* __restrict__ Kw, const float* __restrict__ Kb,
            const float* __restrict__ Qw, const float* __restrict__ Qb,
            const float* __restrict__ Vw, const float* __restrict__ Vb,
            float* __restrict__ w_out, float* __restrict__ x_out)
{
    extern __shared__ float smem[];
    const int h = blockIdx.x, b = blockIdx.y;
    const int tid = threadIdx.x, tx = tid & 15, ty = tid >> 4;

    float* s_x  = smem;                     // 64*IN_DIM (reused as s_w later)
    float* s_se = s_x  + 64 * IN_DIM;       // 64*128
    float* s_kT = s_se + 64 * 128;          // 128*68  (k^T: [e][m])
    float* s_q  = s_kT + 128 * 68;          // 64*128
    float* s_v  = s_q  + 64 * 128;          // 64*32
    float* s_wt = s_v  + 64 * 32;           // 2 * 32*132 staging
    float* s_w  = s_x;                      // 64*64 overlay

    // Load input tile x[b] (coalesced float4); fenced by gemm's first barrier.
    const float* gx = x + (size_t)b * 64 * IN_DIM;
    for (int i = 4 * tid; i < 64 * IN_DIM; i += 2048)
        *(float4*)&s_x[i] = *(const float4*)&gx[i];

    // Phase 1: se = lrelu(x @ Ew^T + Eb)
    gemm<8>(s_x, IN_DIM, IN_DIM,
            Ew + (size_t)h * 128 * IN_DIM, Eb + h * 128,
            s_wt, s_se, 128, false, true, tx, ty, tid);
    // Phase 2: k^T, q, v
    gemm<8>(s_se, 128, 128, Kw + (size_t)h * 128 * 128, Kb + h * 128,
            s_wt, s_kT, 68, true, false, tx, ty, tid);
    gemm<8>(s_se, 128, 128, Qw + (size_t)h * 128 * 128, Qb + h * 128,
            s_wt, s_q, 128, false, false, tx, ty, tid);
    gemm<2>(s_se, 128, 128, Vw + (size_t)h * 32 * 128, Vb + h * 32,
            s_wt, s_v, 32, false, true, tx, ty, tid);
    __syncthreads();

    // Phase 3: scores (64x64, K=128) + row softmax. micro-tile 2x4 (2 pairs).
    ull sacc[2][2] = {{0ull, 0ull}, {0ull, 0ull}};
#pragma unroll 8
    for (int k4 = 0; k4 < 32; ++k4) {
        float4 a0 = *(const float4*)&s_q[(2 * ty)     * 128 + 4 * k4];
        float4 a1 = *(const float4*)&s_q[(2 * ty + 1) * 128 + 4 * k4];
#pragma unroll
        for (int q = 0; q < 4; ++q) {
            float av0 = (&a0.x)[q], av1 = (&a1.x)[q];
            ull ap0 = pack2(av0, av0);
            ull ap1 = pack2(av1, av1);
            const ull* bp = (const ull*)&s_kT[(4 * k4 + q) * 68 + 4 * tx];
            ull b0 = bp[0], b1 = bp[1];
            sacc[0][0] = fma2(ap0, b0, sacc[0][0]);
            sacc[0][1] = fma2(ap0, b1, sacc[0][1]);
            sacc[1][0] = fma2(ap1, b0, sacc[1][0]);
            sacc[1][1] = fma2(ap1, b1, sacc[1][1]);
        }
    }
    const float SCALE = 0.08838834764831845f;  // 1/sqrt(128)
    float* wg = w_out + (((size_t)h * Bb + b) * 64) * 64;
#pragma unroll
    for (int i = 0; i < 2; ++i) {
        float sc[4];
        unpack2(sacc[i][0], sc[0], sc[1]);
        unpack2(sacc[i][1], sc[2], sc[3]);
        float m = -3.0e38f;
#pragma unroll
        for (int j = 0; j < 4; ++j) { sc[j] *= SCALE; m = fmaxf(m, sc[j]); }
#pragma unroll
        for (int off = 1; off < 16; off <<= 1)
            m = fmaxf(m, __shfl_xor_sync(0xffffffffu, m, off));
        float s = 0.0f;
#pragma unroll
        for (int j = 0; j < 4; ++j) { sc[j] = __expf(sc[j] - m); s += sc[j]; }
#pragma unroll
        for (int off = 1; off < 16; off <<= 1)
            s += __shfl_xor_sync(0xffffffffu, s, off);
        float inv = 1.0f / s;
        float4 wv = make_float4(sc[0] * inv, sc[1] * inv, sc[2] * inv, sc[3] * inv);
        int row = 2 * ty + i;
        *(float4*)&s_w[row * 64 + 4 * tx] = wv;
        *(float4*)&wg[(size_t)row * 64 + 4 * tx] = wv;
    }
    __syncthreads();

    // Phase 4: att = w @ v (64x32, K=64). micro-tile 2x2 (1 pair).
    ull aacc[2] = {0ull, 0ull};
#pragma unroll 8
    for (int k4 = 0; k4 < 16; ++k4) {
        float4 a0 = *(const float4*)&s_w[(2 * ty)     * 64 + 4 * k4];
        float4 a1 = *(const float4*)&s_w[(2 * ty + 1) * 64 + 4 * k4];
#pragma unroll
        for (int q = 0; q < 4; ++q) {
            float av0 = (&a0.x)[q], av1 = (&a1.x)[q];
            ull bb = *(const ull*)&s_v[(4 * k4 + q) * 32 + 2 * tx];
            aacc[0] = fma2(pack2(av0, av0), bb, aacc[0]);
            aacc[1] = fma2(pack2(av1, av1), bb, aacc[1]);
        }
    }
#pragma unroll
    for (int i = 0; i < 2; ++i) {
        float v0, v1; unpack2(aacc[i], v0, v1);
        int row = 2 * ty + i;
        *(float2*)&x_out[((size_t)b * 64 + row) * 128 + h * 32 + 2 * tx] =
            make_float2(v0, v1);
    }
}

// ---------------------------------------------------------------------------
// Final MLP + softmax policy head (unchanged — ~2% of runtime).
// ---------------------------------------------------------------------------
__global__ void __launch_bounds__(256)
mlp_kernel(const float* __restrict__ x,
           const float* __restrict__ F1w, const float* __restrict__ F1b,
           const float* __restrict__ F2w, const float* __restrict__ F2b,
           float* __restrict__ out)
{
    __shared__ float sF1[128 * 65];
    __shared__ float sF2[16 * 64];
    __shared__ float sB1[64];
    __shared__ float sB2[16];
    __shared__ float sx[8][2][128];

    const int tid = threadIdx.x, lane = tid & 31, warp = tid >> 5;

    for (int idx = tid; idx < 64 * 128; idx += 256) {
        int o = idx >> 7, d = idx & 127;
        sF1[d * 65 + o] = F1w[idx];
    }
    for (int idx = tid; idx < 16 * 64; idx += 256) sF2[idx] = F2w[idx];
    if (tid < 64) sB1[tid] = F1b[tid];
    if (tid < 16) sB2[tid] = F2b[tid];
    __syncthreads();

    const int NGRP = (Bb * Nn) / 2;
    for (int g = blockIdx.x * 8 + warp; g < NGRP; g += gridDim.x * 8) {
        int row0 = g * 2;
#pragma unroll
        for (int r = 0; r < 2; ++r)
            *(float4*)&sx[warp][r][lane * 4] =
                *(const float4*)&x[(size_t)(row0 + r) * 128 + lane * 4];
        __syncwarp();

        float h0[2], h1[2];
        h0[0] = h0[1] = sB1[lane];
        h1[0] = h1[1] = sB1[lane + 32];
#pragma unroll 8
        for (int d = 0; d < 128; ++d) {
            float w0 = sF1[d * 65 + lane];
            float w1 = sF1[d * 65 + 32 + lane];
#pragma unroll
            for (int r = 0; r < 2; ++r) {
                float xv = sx[warp][r][d];
                h0[r] = fmaf(xv, w0, h0[r]);
                h1[r] = fmaf(xv, w1, h1[r]);
            }
        }
#pragma unroll
        for (int r = 0; r < 2; ++r) { h0[r] = LRELU(h0[r]); h1[r] = LRELU(h1[r]); }

#pragma unroll
        for (int r = 0; r < 2; ++r) {
            float p[16];
#pragma unroll
            for (int j = 0; j < 16; ++j) {
                float t = fmaf(h0[r], sF2[j * 64 + lane],
                               h1[r] * sF2[j * 64 + 32 + lane]);
#pragma unroll
                for (int off = 16; off > 0; off >>= 1)
                    t += __shfl_xor_sync(0xffffffffu, t, off);
                p[j] = t + sB2[j];
            }
            float m = p[0];
#pragma unroll
            for (int j = 1; j < 16; ++j) m = fmaxf(m, p[j]);
            float s = 0.0f;
#pragma unroll
            for (int j = 0; j < 16; ++j) { p[j] = __expf(p[j] - m); s += p[j]; }
            float inv = 1.0f / s;
            float mine = 0.0f;
#pragma unroll
            for (int j = 0; j < 16; ++j) mine = (lane == j) ? p[j] * inv : mine;
            if (lane < 16) out[(size_t)(row0 + r) * 16 + lane] = mine;
        }
        __syncwarp();
    }
}

// ---------------------------------------------------------------------------
extern "C" void kernel_launch(void* const* d_in, const int* in_sizes, int n_in,
                              void* d_out, int out_size)
{
    const float* states = (const float*)d_in[0];
    const float* E1w = (const float*)d_in[1];  const float* E1b = (const float*)d_in[2];
    const float* K1w = (const float*)d_in[3];  const float* K1b = (const float*)d_in[4];
    const float* Q1w = (const float*)d_in[5];  const float* Q1b = (const float*)d_in[6];
    const float* V1w = (const float*)d_in[7];  const float* V1b = (const float*)d_in[8];
    const float* E2w = (const float*)d_in[9];  const float* E2b = (const float*)d_in[10];
    const float* K2w = (const float*)d_in[11]; const float* K2b = (const float*)d_in[12];
    const float* Q2w = (const float*)d_in[13]; const float* Q2b = (const float*)d_in[14];
    const float* V2w = (const float*)d_in[15]; const float* V2b = (const float*)d_in[16];
    const float* F1w = (const float*)d_in[17]; const float* F1b = (const float*)d_in[18];
    const float* F2w = (const float*)d_in[19]; const float* F2b = (const float*)d_in[20];

    float* out    = (float*)d_out;
    float* policy = out;                                      // [512,64,16]
    float* w1     = out + (size_t)Bb * Nn * FOUT;             // [4,512,64,64]
    float* w2     = w1 + (size_t)Hh * Bb * Nn * Nn;           // [4,512,64,64]

    float* x1p = nullptr; float* x2p = nullptr;
    cudaGetSymbolAddress((void**)&x1p, g_x1);
    cudaGetSymbolAddress((void**)&x2p, g_x2);

    const int SMEM1 = (64*256 + 64*128 + 128*68 + 64*128 + 64*32 + 2*32*132) * 4;
    const int SMEM2 = (64*128 + 64*128 + 128*68 + 64*128 + 64*32 + 2*32*132) * 4;
    cudaFuncSetAttribute(attn_kernel<256>, cudaFuncAttributeMaxDynamicSharedMemorySize, SMEM1);
    cudaFuncSetAttribute(attn_kernel<128>, cudaFuncAttributeMaxDynamicSharedMemorySize, SMEM2);

    dim3 grid(Hh, Bb);
    attn_kernel<256><<<grid, 512, SMEM1>>>(states, E1w, E1b, K1w, K1b,
                                           Q1w, Q1b, V1w, V1b, w1, x1p);
    attn_kernel<128><<<grid, 512, SMEM2>>>(x1p, E2w, E2b, K2w, K2b,
                                           Q2w, Q2b, V2w, V2b, w2, x2p);
    mlp_kernel<<<512, 256>>>(x2p, F1w, F1b, F2w, F2b, policy);
}

// round 8
// speedup vs baseline: 1.5168x; 1.5150x over previous
#include <cuda_runtime.h>
#include <cstdint>

#define LRELU(v) ((v) > 0.0f ? (v) : 0.01f * (v))
using ull = unsigned long long;

static constexpr int Bb   = 512;
static constexpr int Nn   = 64;
static constexpr int Hh   = 4;
static constexpr int FOUT = 16;

// Scratch for inter-stage activations (x1, x2: [B, N, 128])
__device__ float g_x1[(size_t)Bb * Nn * 128];
__device__ float g_x2[(size_t)Bb * Nn * 128];

// ---------------------------------------------------------------------------
// Packed fp32x2 helpers (Blackwell FFMA2 — only reachable via PTX)
// ---------------------------------------------------------------------------
__device__ __forceinline__ ull pack2(float a, float b) {
    ull r;
    asm("mov.b64 %0, {%1, %2};" : "=l"(r) : "f"(a), "f"(b));
    return r;
}
__device__ __forceinline__ void unpack2(ull v, float& a, float& b) {
    asm("mov.b64 {%0, %1}, %2;" : "=f"(a), "=f"(b) : "l"(v));
}
__device__ __forceinline__ ull fma2(ull a, ull b, ull c) {
    ull d;
    asm("fma.rn.f32x2 %0, %1, %2, %3;" : "=l"(d) : "l"(a), "l"(b), "l"(c));
    return d;
}

// ---------------------------------------------------------------------------
// cp.async helpers
// ---------------------------------------------------------------------------
__device__ __forceinline__ uint32_t s2u(const void* p) {
    return (uint32_t)__cvta_generic_to_shared(p);
}
__device__ __forceinline__ void cp4(uint32_t dst, const float* src) {
    asm volatile("cp.async.ca.shared.global [%0], [%1], 4;" :: "r"(dst), "l"(src));
}
__device__ __forceinline__ void cp_commit() {
    asm volatile("cp.async.commit_group;" ::: "memory");
}
template<int N>
__device__ __forceinline__ void cp_wait() {
    asm volatile("cp.async.wait_group %0;" :: "n"(N) : "memory");
}

// ---------------------------------------------------------------------------
// Register-blocked packed GEMM: C[64][NC] = A(smem)[64][K] * W(gmem)[NC][K]^T + b
// 256 threads: tx = tid&15 (16 col-groups), ty = tid>>4 (16 row-groups);
// micro-tile 4 rows x CW cols, accumulated as f32x2 pairs.
// W k-tiles staged transposed [kk][n] (stride 132) via double-buffered cp.async.
// A-loads are float4, amortized over 4 k-steps.
// ---------------------------------------------------------------------------
template<int CW>
__device__ __forceinline__ void gemm(
    const float* __restrict__ sA, int lda, int Kdim,
    const float* __restrict__ gW, const float* __restrict__ gBias,
    float* __restrict__ sWt,              // 2 buffers of 32*132 floats
    float* __restrict__ sOut, int ldo, bool outT, bool relu,
    int tx, int ty, int tid)
{
    constexpr int NC    = CW * 16;
    constexpr int NPAIR = CW / 2;
    ull acc[4][NPAIR];
#pragma unroll
    for (int i = 0; i < 4; ++i)
#pragma unroll
        for (int p = 0; p < NPAIR; ++p) acc[i][p] = 0ull;

    const int kk = tid & 31;
    const int n0 = tid >> 5;               // 0..7
    const int ntiles = Kdim / 32;

    // stage tile t into buffer buf (transposed [kk][n])
    auto stage = [&](int t, int buf) {
        float* dst = sWt + buf * (32 * 132) + kk * 132;
        const float* src = gW + (size_t)t * 32 + kk;
#pragma unroll
        for (int n = n0; n < NC; n += 8)
            cp4(s2u(dst + n), src + (size_t)n * Kdim);
        cp_commit();
    };

    stage(0, 0);
    for (int t = 0; t < ntiles; ++t) {
        if (t + 1 < ntiles) { stage(t + 1, (t + 1) & 1); cp_wait<1>(); }
        else                { cp_wait<0>(); }
        __syncthreads();                   // tile t ready; fences prior phase smem
        const float* w = sWt + (t & 1) * (32 * 132);
        const float* ar = sA + (4 * ty) * lda + t * 32;
#pragma unroll
        for (int k4 = 0; k4 < 8; ++k4) {
            float4 a0 = *(const float4*)(ar + 0 * lda + 4 * k4);
            float4 a1 = *(const float4*)(ar + 1 * lda + 4 * k4);
            float4 a2 = *(const float4*)(ar + 2 * lda + 4 * k4);
            float4 a3 = *(const float4*)(ar + 3 * lda + 4 * k4);
#pragma unroll
            for (int q = 0; q < 4; ++q) {
                ull ap0 = pack2((&a0.x)[q], (&a0.x)[q]);
                ull ap1 = pack2((&a1.x)[q], (&a1.x)[q]);
                ull ap2 = pack2((&a2.x)[q], (&a2.x)[q]);
                ull ap3 = pack2((&a3.x)[q], (&a3.x)[q]);
                const ull* bp = (const ull*)(w + (4 * k4 + q) * 132 + CW * tx);
#pragma unroll
                for (int p = 0; p < NPAIR; ++p) {
                    ull bb = bp[p];
                    acc[0][p] = fma2(ap0, bb, acc[0][p]);
                    acc[1][p] = fma2(ap1, bb, acc[1][p]);
                    acc[2][p] = fma2(ap2, bb, acc[2][p]);
                    acc[3][p] = fma2(ap3, bb, acc[3][p]);
                }
            }
        }
        __syncthreads();                   // safe to overwrite buffer t&1
    }

    // epilogue
#pragma unroll
    for (int p = 0; p < NPAIR; ++p) {
        int col = CW * tx + 2 * p;
        float b0 = gBias[col], b1 = gBias[col + 1];
#pragma unroll
        for (int i = 0; i < 4; ++i) {
            float v0, v1; unpack2(acc[i][p], v0, v1);
            v0 += b0; v1 += b1;
            if (relu) { v0 = LRELU(v0); v1 = LRELU(v1); }
            int row = 4 * ty + i;
            if (outT) { sOut[col * ldo + row] = v0; sOut[(col + 1) * ldo + row] = v1; }
            else      { sOut[row * ldo + col] = v0; sOut[row * ldo + col + 1]   = v1; }
        }
    }
}

// ---------------------------------------------------------------------------
// Fused attention block: one CTA (256 threads) per (head h, batch b).
// ---------------------------------------------------------------------------
template<int IN_DIM>
__global__ void __launch_bounds__(256, 1)
attn_kernel(const float* __restrict__ x,
            const float* __restrict__ Ew, const float* __restrict__ Eb,
            const float* __restrict__ Kw, const float* __restrict__ Kb,
            const float* __restrict__ Qw, const float* __restrict__ Qb,
            const float* __restrict__ Vw, const float* __restrict__ Vb,
            float* __restrict__ w_out, float* __restrict__ x_out)
{
    extern __shared__ float smem[];
    const int h = blockIdx.x, b = blockIdx.y;
    const int tid = threadIdx.x, tx = tid & 15, ty = tid >> 4;

    float* s_x  = smem;                     // 64*IN_DIM (reused as s_w later)
    float* s_se = s_x  + 64 * IN_DIM;       // 64*128
    float* s_kT = s_se + 64 * 128;          // 128*68  (k^T: [e][m])
    float* s_q  = s_kT + 128 * 68;          // 64*128
    float* s_v  = s_q  + 64 * 128;          // 64*32
    float* s_wt = s_v  + 64 * 32;           // 2 * 32*132 staging
    float* s_w  = s_x;                      // 64*64 overlay

    // Load input tile x[b] (coalesced float4); fenced by gemm's first barrier.
    const float* gx = x + (size_t)b * 64 * IN_DIM;
    for (int i = 4 * tid; i < 64 * IN_DIM; i += 1024)
        *(float4*)&s_x[i] = *(const float4*)&gx[i];

    // Phase 1: se = lrelu(x @ Ew^T + Eb)
    gemm<8>(s_x, IN_DIM, IN_DIM,
            Ew + (size_t)h * 128 * IN_DIM, Eb + h * 128,
            s_wt, s_se, 128, false, true, tx, ty, tid);
    // Phase 2: k^T, q, v
    gemm<8>(s_se, 128, 128, Kw + (size_t)h * 128 * 128, Kb + h * 128,
            s_wt, s_kT, 68, true, false, tx, ty, tid);
    gemm<8>(s_se, 128, 128, Qw + (size_t)h * 128 * 128, Qb + h * 128,
            s_wt, s_q, 128, false, false, tx, ty, tid);
    gemm<2>(s_se, 128, 128, Vw + (size_t)h * 32 * 128, Vb + h * 32,
            s_wt, s_v, 32, false, true, tx, ty, tid);
    __syncthreads();

    // Phase 3: scores (64x64, K=128) + row softmax. micro-tile 4 rows x 4 cols.
    ull sacc[4][2];
#pragma unroll
    for (int i = 0; i < 4; ++i) { sacc[i][0] = 0ull; sacc[i][1] = 0ull; }
#pragma unroll 4
    for (int k4 = 0; k4 < 32; ++k4) {
        float4 a0 = *(const float4*)&s_q[(4 * ty + 0) * 128 + 4 * k4];
        float4 a1 = *(const float4*)&s_q[(4 * ty + 1) * 128 + 4 * k4];
        float4 a2 = *(const float4*)&s_q[(4 * ty + 2) * 128 + 4 * k4];
        float4 a3 = *(const float4*)&s_q[(4 * ty + 3) * 128 + 4 * k4];
#pragma unroll
        for (int q = 0; q < 4; ++q) {
            const ull* bp = (const ull*)&s_kT[(4 * k4 + q) * 68 + 4 * tx];
            ull b0 = bp[0], b1 = bp[1];
            ull ap0 = pack2((&a0.x)[q], (&a0.x)[q]);
            ull ap1 = pack2((&a1.x)[q], (&a1.x)[q]);
            ull ap2 = pack2((&a2.x)[q], (&a2.x)[q]);
            ull ap3 = pack2((&a3.x)[q], (&a3.x)[q]);
            sacc[0][0] = fma2(ap0, b0, sacc[0][0]);
            sacc[0][1] = fma2(ap0, b1, sacc[0][1]);
            sacc[1][0] = fma2(ap1, b0, sacc[1][0]);
            sacc[1][1] = fma2(ap1, b1, sacc[1][1]);
            sacc[2][0] = fma2(ap2, b0, sacc[2][0]);
            sacc[2][1] = fma2(ap2, b1, sacc[2][1]);
            sacc[3][0] = fma2(ap3, b0, sacc[3][0]);
            sacc[3][1] = fma2(ap3, b1, sacc[3][1]);
        }
    }
    const float SCALE = 0.08838834764831845f;  // 1/sqrt(128)
    float* wg = w_out + (((size_t)h * Bb + b) * 64) * 64;
#pragma unroll
    for (int i = 0; i < 4; ++i) {
        float sc[4];
        unpack2(sacc[i][0], sc[0], sc[1]);
        unpack2(sacc[i][1], sc[2], sc[3]);
        float m = -3.0e38f;
#pragma unroll
        for (int j = 0; j < 4; ++j) { sc[j] *= SCALE; m = fmaxf(m, sc[j]); }
#pragma unroll
        for (int off = 1; off < 16; off <<= 1)
            m = fmaxf(m, __shfl_xor_sync(0xffffffffu, m, off));
        float s = 0.0f;
#pragma unroll
        for (int j = 0; j < 4; ++j) { sc[j] = __expf(sc[j] - m); s += sc[j]; }
#pragma unroll
        for (int off = 1; off < 16; off <<= 1)
            s += __shfl_xor_sync(0xffffffffu, s, off);
        float inv = 1.0f / s;
        float4 wv = make_float4(sc[0] * inv, sc[1] * inv, sc[2] * inv, sc[3] * inv);
        int row = 4 * ty + i;
        *(float4*)&s_w[row * 64 + 4 * tx] = wv;
        *(float4*)&wg[(size_t)row * 64 + 4 * tx] = wv;
    }
    __syncthreads();

    // Phase 4: att = w @ v (64x32, K=64). micro-tile 4 rows x 2 cols.
    ull aacc[4] = {0ull, 0ull, 0ull, 0ull};
#pragma unroll 4
    for (int k4 = 0; k4 < 16; ++k4) {
        float4 a0 = *(const float4*)&s_w[(4 * ty + 0) * 64 + 4 * k4];
        float4 a1 = *(const float4*)&s_w[(4 * ty + 1) * 64 + 4 * k4];
        float4 a2 = *(const float4*)&s_w[(4 * ty + 2) * 64 + 4 * k4];
        float4 a3 = *(const float4*)&s_w[(4 * ty + 3) * 64 + 4 * k4];
#pragma unroll
        for (int q = 0; q < 4; ++q) {
            ull bb = *(const ull*)&s_v[(4 * k4 + q) * 32 + 2 * tx];
            aacc[0] = fma2(pack2((&a0.x)[q], (&a0.x)[q]), bb, aacc[0]);
            aacc[1] = fma2(pack2((&a1.x)[q], (&a1.x)[q]), bb, aacc[1]);
            aacc[2] = fma2(pack2((&a2.x)[q], (&a2.x)[q]), bb, aacc[2]);
            aacc[3] = fma2(pack2((&a3.x)[q], (&a3.x)[q]), bb, aacc[3]);
        }
    }
#pragma unroll
    for (int i = 0; i < 4; ++i) {
        float v0, v1; unpack2(aacc[i], v0, v1);
        int row = 4 * ty + i;
        *(float2*)&x_out[((size_t)b * 64 + row) * 128 + h * 32 + 2 * tx] =
            make_float2(v0, v1);
    }
}

// ---------------------------------------------------------------------------
// Final MLP + softmax policy head (~2% of runtime).
// ---------------------------------------------------------------------------
__global__ void __launch_bounds__(256)
mlp_kernel(const float* __restrict__ x,
           const float* __restrict__ F1w, const float* __restrict__ F1b,
           const float* __restrict__ F2w, const float* __restrict__ F2b,
           float* __restrict__ out)
{
    __shared__ float sF1[128 * 65];
    __shared__ float sF2[16 * 64];
    __shared__ float sB1[64];
    __shared__ float sB2[16];
    __shared__ float sx[8][2][128];

    const int tid = threadIdx.x, lane = tid & 31, warp = tid >> 5;

    for (int idx = tid; idx < 64 * 128; idx += 256) {
        int o = idx >> 7, d = idx & 127;
        sF1[d * 65 + o] = F1w[idx];
    }
    for (int idx = tid; idx < 16 * 64; idx += 256) sF2[idx] = F2w[idx];
    if (tid < 64) sB1[tid] = F1b[tid];
    if (tid < 16) sB2[tid] = F2b[tid];
    __syncthreads();

    const int NGRP = (Bb * Nn) / 2;
    for (int g = blockIdx.x * 8 + warp; g < NGRP; g += gridDim.x * 8) {
        int row0 = g * 2;
#pragma unroll
        for (int r = 0; r < 2; ++r)
            *(float4*)&sx[warp][r][lane * 4] =
                *(const float4*)&x[(size_t)(row0 + r) * 128 + lane * 4];
        __syncwarp();

        float h0[2], h1[2];
        h0[0] = h0[1] = sB1[lane];
        h1[0] = h1[1] = sB1[lane + 32];
#pragma unroll 8
        for (int d = 0; d < 128; ++d) {
            float w0 = sF1[d * 65 + lane];
            float w1 = sF1[d * 65 + 32 + lane];
#pragma unroll
            for (int r = 0; r < 2; ++r) {
                float xv = sx[warp][r][d];
                h0[r] = fmaf(xv, w0, h0[r]);
                h1[r] = fmaf(xv, w1, h1[r]);
            }
        }
#pragma unroll
        for (int r = 0; r < 2; ++r) { h0[r] = LRELU(h0[r]); h1[r] = LRELU(h1[r]); }

#pragma unroll
        for (int r = 0; r < 2; ++r) {
            float p[16];
#pragma unroll
            for (int j = 0; j < 16; ++j) {
                float t = fmaf(h0[r], sF2[j * 64 + lane],
                               h1[r] * sF2[j * 64 + 32 + lane]);
#pragma unroll
                for (int off = 16; off > 0; off >>= 1)
                    t += __shfl_xor_sync(0xffffffffu, t, off);
                p[j] = t + sB2[j];
            }
            float m = p[0];
#pragma unroll
            for (int j = 1; j < 16; ++j) m = fmaxf(m, p[j]);
            float s = 0.0f;
#pragma unroll
            for (int j = 0; j < 16; ++j) { p[j] = __expf(p[j] - m); s += p[j]; }
            float inv = 1.0f / s;
            float mine = 0.0f;
#pragma unroll
            for (int j = 0; j < 16; ++j) mine = (lane == j) ? p[j] * inv : mine;
            if (lane < 16) out[(size_t)(row0 + r) * 16 + lane] = mine;
        }
        __syncwarp();
    }
}

// ---------------------------------------------------------------------------
extern "C" void kernel_launch(void* const* d_in, const int* in_sizes, int n_in,
                              void* d_out, int out_size)
{
    const float* states = (const float*)d_in[0];
    const float* E1w = (const float*)d_in[1];  const float* E1b = (const float*)d_in[2];
    const float* K1w = (const float*)d_in[3];  const float* K1b = (const float*)d_in[4];
    const float* Q1w = (const float*)d_in[5];  const float* Q1b = (const float*)d_in[6];
    const float* V1w = (const float*)d_in[7];  const float* V1b = (const float*)d_in[8];
    const float* E2w = (const float*)d_in[9];  const float* E2b = (const float*)d_in[10];
    const float* K2w = (const float*)d_in[11]; const float* K2b = (const float*)d_in[12];
    const float* Q2w = (const float*)d_in[13]; const float* Q2b = (const float*)d_in[14];
    const float* V2w = (const float*)d_in[15]; const float* V2b = (const float*)d_in[16];
    const float* F1w = (const float*)d_in[17]; const float* F1b = (const float*)d_in[18];
    const float* F2w = (const float*)d_in[19]; const float* F2b = (const float*)d_in[20];

    float* out    = (float*)d_out;
    float* policy = out;                                      // [512,64,16]
    float* w1     = out + (size_t)Bb * Nn * FOUT;             // [4,512,64,64]
    float* w2     = w1 + (size_t)Hh * Bb * Nn * Nn;           // [4,512,64,64]

    float* x1p = nullptr; float* x2p = nullptr;
    cudaGetSymbolAddress((void**)&x1p, g_x1);
    cudaGetSymbolAddress((void**)&x2p, g_x2);

    const int SMEM1 = (64*256 + 64*128 + 128*68 + 64*128 + 64*32 + 2*32*132) * 4;
    const int SMEM2 = (64*128 + 64*128 + 128*68 + 64*128 + 64*32 + 2*32*132) * 4;
    cudaFuncSetAttribute(attn_kernel<256>, cudaFuncAttributeMaxDynamicSharedMemorySize, SMEM1);
    cudaFuncSetAttribute(attn_kernel<128>, cudaFuncAttributeMaxDynamicSharedMemorySize, SMEM2);

    dim3 grid(Hh, Bb);
    attn_kernel<256><<<grid, 256, SMEM1>>>(states, E1w, E1b, K1w, K1b,
                                           Q1w, Q1b, V1w, V1b, w1, x1p);
    attn_kernel<128><<<grid, 256, SMEM2>>>(x1p, E2w, E2b, K2w, K2b,
                                           Q2w, Q2b, V2w, V2b, w2, x2p);
    mlp_kernel<<<512, 256>>>(x2p, F1w, F1b, F2w, F2b, policy);
}

// round 9
// speedup vs baseline: 2.0236x; 1.3341x over previous
#include <cuda_runtime.h>
#include <cstdint>

#define LRELU(v) ((v) > 0.0f ? (v) : 0.01f * (v))
using ull = unsigned long long;

static constexpr int Bb   = 512;
static constexpr int Nn   = 64;
static constexpr int Hh   = 4;
static constexpr int FOUT = 16;

// Scratch for inter-stage activations (x1, x2: [B, N, 128])
__device__ float g_x1[(size_t)Bb * Nn * 128];
__device__ float g_x2[(size_t)Bb * Nn * 128];

// ---------------------------------------------------------------------------
// Packed fp32x2 helpers (Blackwell FFMA2 — only reachable via PTX)
// ---------------------------------------------------------------------------
__device__ __forceinline__ ull pack2(float a, float b) {
    ull r;
    asm("mov.b64 %0, {%1, %2};" : "=l"(r) : "f"(a), "f"(b));
    return r;
}
__device__ __forceinline__ void unpack2(ull v, float& a, float& b) {
    asm("mov.b64 {%0, %1}, %2;" : "=f"(a), "=f"(b) : "l"(v));
}
__device__ __forceinline__ ull fma2(ull a, ull b, ull c) {
    ull d;
    asm("fma.rn.f32x2 %0, %1, %2, %3;" : "=l"(d) : "l"(a), "l"(b), "l"(c));
    return d;
}

// ---------------------------------------------------------------------------
// cp.async helpers
// ---------------------------------------------------------------------------
__device__ __forceinline__ uint32_t s2u(const void* p) {
    return (uint32_t)__cvta_generic_to_shared(p);
}
__device__ __forceinline__ void cp4(uint32_t dst, const float* src) {
    asm volatile("cp.async.ca.shared.global [%0], [%1], 4;" :: "r"(dst), "l"(src));
}
__device__ __forceinline__ void cp_commit() {
    asm volatile("cp.async.commit_group;" ::: "memory");
}
template<int N>
__device__ __forceinline__ void cp_wait() {
    asm volatile("cp.async.wait_group %0;" :: "n"(N) : "memory");
}

// ---------------------------------------------------------------------------
// Register-blocked packed GEMM: C[64][NC] = A(smem)[64][K] * W(gmem)[NC][K]^T + b
// 256 threads. Thread grid: G = 4*RPT col-groups (tx), 256/G row-groups (ty);
// micro-tile RPT rows x CW=NC/G cols, accumulated as f32x2 pairs.
//   RPT=8 (G=32): warp-uniform ty -> A-loads are pure broadcasts; B = 1 LDS.128/kk.
// W k-tiles staged transposed [kk][n] (stride 132) via double-buffered cp.async.
// ---------------------------------------------------------------------------
template<int NC, int RPT>
__device__ __forceinline__ void gemm(
    const float* __restrict__ sA, int lda, int Kdim,
    const float* __restrict__ gW, const float* __restrict__ gBias,
    float* __restrict__ sWt,              // 2 buffers of 32*132 floats
    float* __restrict__ sOut, int ldo, bool outT, bool relu, int tid)
{
    constexpr int G     = 4 * RPT;        // col groups
    constexpr int CW    = NC / G;         // cols per thread
    constexpr int NPAIR = CW / 2;
    const int tx = tid % G, ty = tid / G;

    ull acc[RPT][NPAIR];
#pragma unroll
    for (int i = 0; i < RPT; ++i)
#pragma unroll
        for (int p = 0; p < NPAIR; ++p) acc[i][p] = 0ull;

    const int kk = tid & 31;
    const int n0 = tid >> 5;               // 0..7
    const int ntiles = Kdim / 32;

    // stage tile t into buffer buf (transposed [kk][n])
    auto stage = [&](int t, int buf) {
        float* dst = sWt + buf * (32 * 132) + kk * 132;
        const float* src = gW + (size_t)t * 32 + kk;
#pragma unroll
        for (int n = n0; n < NC; n += 8)
            cp4(s2u(dst + n), src + (size_t)n * Kdim);
        cp_commit();
    };

    stage(0, 0);
    for (int t = 0; t < ntiles; ++t) {
        if (t + 1 < ntiles) { stage(t + 1, (t + 1) & 1); cp_wait<1>(); }
        else                { cp_wait<0>(); }
        __syncthreads();                   // tile t ready; fences prior phase smem
        const float* w  = sWt + (t & 1) * (32 * 132);
        const float* ar = sA + (RPT * ty) * lda + t * 32;
#pragma unroll
        for (int k4 = 0; k4 < 8; ++k4) {
            float4 a[RPT];
#pragma unroll
            for (int r = 0; r < RPT; ++r)
                a[r] = *(const float4*)(ar + r * lda + 4 * k4);   // broadcast
#pragma unroll
            for (int q = 0; q < 4; ++q) {
                ull ap[RPT];
#pragma unroll
                for (int r = 0; r < RPT; ++r)
                    ap[r] = pack2((&a[r].x)[q], (&a[r].x)[q]);
                const float* brow = w + (4 * k4 + q) * 132 + CW * tx;
                ull bb[NPAIR];
                if constexpr (NPAIR == 2) {
                    ulonglong2 b2 = *(const ulonglong2*)brow;     // LDS.128
                    bb[0] = b2.x; bb[1] = b2.y;
                } else {
                    bb[0] = *(const ull*)brow;                    // LDS.64
                }
#pragma unroll
                for (int r = 0; r < RPT; ++r)
#pragma unroll
                    for (int p = 0; p < NPAIR; ++p)
                        acc[r][p] = fma2(ap[r], bb[p], acc[r][p]);
            }
        }
        __syncthreads();                   // safe to overwrite buffer t&1
    }

    // epilogue
#pragma unroll
    for (int p = 0; p < NPAIR; ++p) {
        int col = CW * tx + 2 * p;
        float b0 = gBias[col], b1 = gBias[col + 1];
#pragma unroll
        for (int i = 0; i < RPT; ++i) {
            float v0, v1; unpack2(acc[i][p], v0, v1);
            v0 += b0; v1 += b1;
            if (relu) { v0 = LRELU(v0); v1 = LRELU(v1); }
            int row = RPT * ty + i;
            if (outT) { sOut[col * ldo + row] = v0; sOut[(col + 1) * ldo + row] = v1; }
            else      { sOut[row * ldo + col] = v0; sOut[row * ldo + col + 1]   = v1; }
        }
    }
}

// ---------------------------------------------------------------------------
// Fused attention block: one CTA (256 threads) per (head h, batch b).
// ---------------------------------------------------------------------------
template<int IN_DIM>
__global__ void __launch_bounds__(256, 1)
attn_kernel(const float* __restrict__ x,
            const float* __restrict__ Ew, const float* __restrict__ Eb,
            const float* __restrict__ Kw, const float* __restrict__ Kb,
            const float* __restrict__ Qw, const float* __restrict__ Qb,
            const float* __restrict__ Vw, const float* __restrict__ Vb,
            float* __restrict__ w_out, float* __restrict__ x_out)
{
    extern __shared__ float smem[];
    const int h = blockIdx.x, b = blockIdx.y;
    const int tid = threadIdx.x;

    float* s_x  = smem;                     // 64*IN_DIM (reused as s_w later)
    float* s_se = s_x  + 64 * IN_DIM;       // 64*128
    float* s_kT = s_se + 64 * 128;          // 128*68  (k^T: [e][m])
    float* s_q  = s_kT + 128 * 68;          // 64*128
    float* s_v  = s_q  + 64 * 128;          // 64*32
    float* s_wt = s_v  + 64 * 32;           // 2 * 32*132 staging
    float* s_w  = s_x;                      // 64*64 overlay

    // Load input tile x[b] (coalesced float4); fenced by gemm's first barrier.
    const float* gx = x + (size_t)b * 64 * IN_DIM;
    for (int i = 4 * tid; i < 64 * IN_DIM; i += 1024)
        *(float4*)&s_x[i] = *(const float4*)&gx[i];

    // Phase 1: se = lrelu(x @ Ew^T + Eb)     (8 rows x 4 cols per thread)
    gemm<128, 8>(s_x, IN_DIM, IN_DIM,
                 Ew + (size_t)h * 128 * IN_DIM, Eb + h * 128,
                 s_wt, s_se, 128, false, true, tid);
    // Phase 2: k^T, q (8x4), v (4x2)
    gemm<128, 8>(s_se, 128, 128, Kw + (size_t)h * 128 * 128, Kb + h * 128,
                 s_wt, s_kT, 68, true, false, tid);
    gemm<128, 8>(s_se, 128, 128, Qw + (size_t)h * 128 * 128, Qb + h * 128,
                 s_wt, s_q, 128, false, false, tid);
    gemm<32, 4>(s_se, 128, 128, Vw + (size_t)h * 32 * 128, Vb + h * 32,
                s_wt, s_v, 32, false, true, tid);
    __syncthreads();

    // Phase 3: scores (64x64, K=128) + row softmax.
    // Thread grid 32(tx) x 8(ty): 8 rows x 2 cols. A-loads broadcast, B LDS.64.
    {
        const int tx = tid & 31, ty = tid >> 5;
        ull sacc[8];
#pragma unroll
        for (int i = 0; i < 8; ++i) sacc[i] = 0ull;
#pragma unroll 4
        for (int k4 = 0; k4 < 32; ++k4) {
            float4 a[8];
#pragma unroll
            for (int r = 0; r < 8; ++r)
                a[r] = *(const float4*)&s_q[(8 * ty + r) * 128 + 4 * k4];
#pragma unroll
            for (int q = 0; q < 4; ++q) {
                ull bb = *(const ull*)&s_kT[(4 * k4 + q) * 68 + 2 * tx];
#pragma unroll
                for (int r = 0; r < 8; ++r)
                    sacc[r] = fma2(pack2((&a[r].x)[q], (&a[r].x)[q]), bb, sacc[r]);
            }
        }
        const float SCALE = 0.08838834764831845f;  // 1/sqrt(128)
        float* wg = w_out + (((size_t)h * Bb + b) * 64) * 64;
#pragma unroll
        for (int i = 0; i < 8; ++i) {
            float sc0, sc1; unpack2(sacc[i], sc0, sc1);
            sc0 *= SCALE; sc1 *= SCALE;
            float m = fmaxf(sc0, sc1);
#pragma unroll
            for (int off = 1; off < 32; off <<= 1)
                m = fmaxf(m, __shfl_xor_sync(0xffffffffu, m, off));
            sc0 = __expf(sc0 - m); sc1 = __expf(sc1 - m);
            float s = sc0 + sc1;
#pragma unroll
            for (int off = 1; off < 32; off <<= 1)
                s += __shfl_xor_sync(0xffffffffu, s, off);
            float inv = 1.0f / s;
            float2 wv = make_float2(sc0 * inv, sc1 * inv);
            int row = 8 * ty + i;
            *(float2*)&s_w[row * 64 + 2 * tx] = wv;
            *(float2*)&wg[(size_t)row * 64 + 2 * tx] = wv;
        }
    }
    __syncthreads();

    // Phase 4: att = w @ v (64x32, K=64). Thread grid 16x16: 4 rows x 2 cols.
    {
        const int tx = tid & 15, ty = tid >> 4;
        ull aacc[4] = {0ull, 0ull, 0ull, 0ull};
#pragma unroll 4
        for (int k4 = 0; k4 < 16; ++k4) {
            float4 a0 = *(const float4*)&s_w[(4 * ty + 0) * 64 + 4 * k4];
            float4 a1 = *(const float4*)&s_w[(4 * ty + 1) * 64 + 4 * k4];
            float4 a2 = *(const float4*)&s_w[(4 * ty + 2) * 64 + 4 * k4];
            float4 a3 = *(const float4*)&s_w[(4 * ty + 3) * 64 + 4 * k4];
#pragma unroll
            for (int q = 0; q < 4; ++q) {
                ull bb = *(const ull*)&s_v[(4 * k4 + q) * 32 + 2 * tx];
                aacc[0] = fma2(pack2((&a0.x)[q], (&a0.x)[q]), bb, aacc[0]);
                aacc[1] = fma2(pack2((&a1.x)[q], (&a1.x)[q]), bb, aacc[1]);
                aacc[2] = fma2(pack2((&a2.x)[q], (&a2.x)[q]), bb, aacc[2]);
                aacc[3] = fma2(pack2((&a3.x)[q], (&a3.x)[q]), bb, aacc[3]);
            }
        }
#pragma unroll
        for (int i = 0; i < 4; ++i) {
            float v0, v1; unpack2(aacc[i], v0, v1);
            int row = 4 * ty + i;
            *(float2*)&x_out[((size_t)b * 64 + row) * 128 + h * 32 + 2 * tx] =
                make_float2(v0, v1);
        }
    }
}

// ---------------------------------------------------------------------------
// Final MLP + softmax policy head (~5% of runtime).
// ---------------------------------------------------------------------------
__global__ void __launch_bounds__(256)
mlp_kernel(const float* __restrict__ x,
           const float* __restrict__ F1w, const float* __restrict__ F1b,
           const float* __restrict__ F2w, const float* __restrict__ F2b,
           float* __restrict__ out)
{
    __shared__ float sF1[128 * 65];
    __shared__ float sF2[16 * 64];
    __shared__ float sB1[64];
    __shared__ float sB2[16];
    __shared__ float sx[8][2][128];

    const int tid = threadIdx.x, lane = tid & 31, warp = tid >> 5;

    for (int idx = tid; idx < 64 * 128; idx += 256) {
        int o = idx >> 7, d = idx & 127;
        sF1[d * 65 + o] = F1w[idx];
    }
    for (int idx = tid; idx < 16 * 64; idx += 256) sF2[idx] = F2w[idx];
    if (tid < 64) sB1[tid] = F1b[tid];
    if (tid < 16) sB2[tid] = F2b[tid];
    __syncthreads();

    const int NGRP = (Bb * Nn) / 2;
    for (int g = blockIdx.x * 8 + warp; g < NGRP; g += gridDim.x * 8) {
        int row0 = g * 2;
#pragma unroll
        for (int r = 0; r < 2; ++r)
            *(float4*)&sx[warp][r][lane * 4] =
                *(const float4*)&x[(size_t)(row0 + r) * 128 + lane * 4];
        __syncwarp();

        float h0[2], h1[2];
        h0[0] = h0[1] = sB1[lane];
        h1[0] = h1[1] = sB1[lane + 32];
#pragma unroll 8
        for (int d = 0; d < 128; ++d) {
            float w0 = sF1[d * 65 + lane];
            float w1 = sF1[d * 65 + 32 + lane];
#pragma unroll
            for (int r = 0; r < 2; ++r) {
                float xv = sx[warp][r][d];
                h0[r] = fmaf(xv, w0, h0[r]);
                h1[r] = fmaf(xv, w1, h1[r]);
            }
        }
#pragma unroll
        for (int r = 0; r < 2; ++r) { h0[r] = LRELU(h0[r]); h1[r] = LRELU(h1[r]); }

#pragma unroll
        for (int r = 0; r < 2; ++r) {
            float p[16];
#pragma unroll
            for (int j = 0; j < 16; ++j) {
                float t = fmaf(h0[r], sF2[j * 64 + lane],
                               h1[r] * sF2[j * 64 + 32 + lane]);
#pragma unroll
                for (int off = 16; off > 0; off >>= 1)
                    t += __shfl_xor_sync(0xffffffffu, t, off);
                p[j] = t + sB2[j];
            }
            float m = p[0];
#pragma unroll
            for (int j = 1; j < 16; ++j) m = fmaxf(m, p[j]);
            float s = 0.0f;
#pragma unroll
            for (int j = 0; j < 16; ++j) { p[j] = __expf(p[j] - m); s += p[j]; }
            float inv = 1.0f / s;
            float mine = 0.0f;
#pragma unroll
            for (int j = 0; j < 16; ++j) mine = (lane == j) ? p[j] * inv : mine;
            if (lane < 16) out[(size_t)(row0 + r) * 16 + lane] = mine;
        }
        __syncwarp();
    }
}

// ---------------------------------------------------------------------------
extern "C" void kernel_launch(void* const* d_in, const int* in_sizes, int n_in,
                              void* d_out, int out_size)
{
    const float* states = (const float*)d_in[0];
    const float* E1w = (const float*)d_in[1];  const float* E1b = (const float*)d_in[2];
    const float* K1w = (const float*)d_in[3];  const float* K1b = (const float*)d_in[4];
    const float* Q1w = (const float*)d_in[5];  const float* Q1b = (const float*)d_in[6];
    const float* V1w = (const float*)d_in[7];  const float* V1b = (const float*)d_in[8];
    const float* E2w = (const float*)d_in[9];  const float* E2b = (const float*)d_in[10];
    const float* K2w = (const float*)d_in[11]; const float* K2b = (const float*)d_in[12];
    const float* Q2w = (const float*)d_in[13]; const float* Q2b = (const float*)d_in[14];
    const float* V2w = (const float*)d_in[15]; const float* V2b = (const float*)d_in[16];
    const float* F1w = (const float*)d_in[17]; const float* F1b = (const float*)d_in[18];
    const float* F2w = (const float*)d_in[19]; const float* F2b = (const float*)d_in[20];

    float* out    = (float*)d_out;
    float* policy = out;                                      // [512,64,16]
    float* w1     = out + (size_t)Bb * Nn * FOUT;             // [4,512,64,64]
    float* w2     = w1 + (size_t)Hh * Bb * Nn * Nn;           // [4,512,64,64]

    float* x1p = nullptr; float* x2p = nullptr;
    cudaGetSymbolAddress((void**)&x1p, g_x1);
    cudaGetSymbolAddress((void**)&x2p, g_x2);

    const int SMEM1 = (64*256 + 64*128 + 128*68 + 64*128 + 64*32 + 2*32*132) * 4;
    const int SMEM2 = (64*128 + 64*128 + 128*68 + 64*128 + 64*32 + 2*32*132) * 4;
    cudaFuncSetAttribute(attn_kernel<256>, cudaFuncAttributeMaxDynamicSharedMemorySize, SMEM1);
    cudaFuncSetAttribute(attn_kernel<128>, cudaFuncAttributeMaxDynamicSharedMemorySize, SMEM2);

    dim3 grid(Hh, Bb);
    attn_kernel<256><<<grid, 256, SMEM1>>>(states, E1w, E1b, K1w, K1b,
                                           Q1w, Q1b, V1w, V1b, w1, x1p);
    attn_kernel<128><<<grid, 256, SMEM2>>>(x1p, E2w, E2b, K2w, K2b,
                                           Q2w, Q2b, V2w, V2b, w2, x2p);
    mlp_kernel<<<512, 256>>>(x2p, F1w, F1b, F2w, F2b, policy);
}

// round 10
// speedup vs baseline: 2.0256x; 1.0010x over previous
#include <cuda_runtime.h>
#include <cstdint>

#define LRELU(v) ((v) > 0.0f ? (v) : 0.01f * (v))
using ull = unsigned long long;

static constexpr int Bb   = 512;
static constexpr int Nn   = 64;
static constexpr int Hh   = 4;
static constexpr int FOUT = 16;

// Scratch for inter-stage activations (x1, x2: [B, N, 128])
__device__ float g_x1[(size_t)Bb * Nn * 128];
__device__ float g_x2[(size_t)Bb * Nn * 128];

// ---------------------------------------------------------------------------
// Packed fp32x2 helpers (Blackwell FFMA2 — only reachable via PTX)
// ---------------------------------------------------------------------------
__device__ __forceinline__ ull pack2(float a, float b) {
    ull r;
    asm("mov.b64 %0, {%1, %2};" : "=l"(r) : "f"(a), "f"(b));
    return r;
}
__device__ __forceinline__ void unpack2(ull v, float& a, float& b) {
    asm("mov.b64 {%0, %1}, %2;" : "=f"(a), "=f"(b) : "l"(v));
}
__device__ __forceinline__ ull fma2(ull a, ull b, ull c) {
    ull d;
    asm("fma.rn.f32x2 %0, %1, %2, %3;" : "=l"(d) : "l"(a), "l"(b), "l"(c));
    return d;
}

// ---------------------------------------------------------------------------
// cp.async helpers
// ---------------------------------------------------------------------------
__device__ __forceinline__ uint32_t s2u(const void* p) {
    return (uint32_t)__cvta_generic_to_shared(p);
}
__device__ __forceinline__ void cp4(uint32_t dst, const float* src) {
    asm volatile("cp.async.ca.shared.global [%0], [%1], 4;" :: "r"(dst), "l"(src));
}
__device__ __forceinline__ void cp_commit() {
    asm volatile("cp.async.commit_group;" ::: "memory");
}
template<int N>
__device__ __forceinline__ void cp_wait() {
    asm volatile("cp.async.wait_group %0;" :: "n"(N) : "memory");
}

// ---------------------------------------------------------------------------
// Register-blocked packed GEMM: C[64][NC] = A(smem)[64][K] * W(gmem)[NC][K]^T + b
// 256 threads. Thread grid: G = 4*RPT col-groups (tx), 256/G row-groups (ty);
// micro-tile RPT rows x CW=NC/G cols, accumulated as f32x2 pairs.
//   RPT=8 (G=32): warp-uniform ty -> A-loads are pure broadcasts; B = 1 LDS.128/kk.
// W k-tiles staged transposed [kk][n] (stride 132) via double-buffered cp.async.
// ---------------------------------------------------------------------------
template<int NC, int RPT>
__device__ __forceinline__ void gemm(
    const float* __restrict__ sA, int lda, int Kdim,
    const float* __restrict__ gW, const float* __restrict__ gBias,
    float* __restrict__ sWt,              // 2 buffers of 32*132 floats
    float* __restrict__ sOut, int ldo, bool outT, bool relu, int tid)
{
    constexpr int G     = 4 * RPT;        // col groups
    constexpr int CW    = NC / G;         // cols per thread
    constexpr int NPAIR = CW / 2;
    const int tx = tid % G, ty = tid / G;

    ull acc[RPT][NPAIR];
#pragma unroll
    for (int i = 0; i < RPT; ++i)
#pragma unroll
        for (int p = 0; p < NPAIR; ++p) acc[i][p] = 0ull;

    const int kk = tid & 31;
    const int n0 = tid >> 5;               // 0..7
    const int ntiles = Kdim / 32;

    // stage tile t into buffer buf (transposed [kk][n])
    auto stage = [&](int t, int buf) {
        float* dst = sWt + buf * (32 * 132) + kk * 132;
        const float* src = gW + (size_t)t * 32 + kk;
#pragma unroll
        for (int n = n0; n < NC; n += 8)
            cp4(s2u(dst + n), src + (size_t)n * Kdim);
        cp_commit();
    };

    stage(0, 0);
    for (int t = 0; t < ntiles; ++t) {
        if (t + 1 < ntiles) { stage(t + 1, (t + 1) & 1); cp_wait<1>(); }
        else                { cp_wait<0>(); }
        __syncthreads();                   // tile t ready; fences prior phase smem
        const float* w  = sWt + (t & 1) * (32 * 132);
        const float* ar = sA + (RPT * ty) * lda + t * 32;
#pragma unroll
        for (int k4 = 0; k4 < 8; ++k4) {
            float4 a[RPT];
#pragma unroll
            for (int r = 0; r < RPT; ++r)
                a[r] = *(const float4*)(ar + r * lda + 4 * k4);   // broadcast
#pragma unroll
            for (int q = 0; q < 4; ++q) {
                ull ap[RPT];
#pragma unroll
                for (int r = 0; r < RPT; ++r)
                    ap[r] = pack2((&a[r].x)[q], (&a[r].x)[q]);
                const float* brow = w + (4 * k4 + q) * 132 + CW * tx;
                ull bb[NPAIR];
                if constexpr (NPAIR == 2) {
                    ulonglong2 b2 = *(const ulonglong2*)brow;     // LDS.128
                    bb[0] = b2.x; bb[1] = b2.y;
                } else {
                    bb[0] = *(const ull*)brow;                    // LDS.64
                }
#pragma unroll
                for (int r = 0; r < RPT; ++r)
#pragma unroll
                    for (int p = 0; p < NPAIR; ++p)
                        acc[r][p] = fma2(ap[r], bb[p], acc[r][p]);
            }
        }
        __syncthreads();                   // safe to overwrite buffer t&1
    }

    // epilogue
#pragma unroll
    for (int p = 0; p < NPAIR; ++p) {
        int col = CW * tx + 2 * p;
        float b0 = gBias[col], b1 = gBias[col + 1];
#pragma unroll
        for (int i = 0; i < RPT; ++i) {
            float v0, v1; unpack2(acc[i][p], v0, v1);
            v0 += b0; v1 += b1;
            if (relu) { v0 = LRELU(v0); v1 = LRELU(v1); }
            int row = RPT * ty + i;
            if (outT) { sOut[col * ldo + row] = v0; sOut[(col + 1) * ldo + row] = v1; }
            else      { sOut[row * ldo + col] = v0; sOut[row * ldo + col + 1]   = v1; }
        }
    }
}

// ---------------------------------------------------------------------------
// Fused attention block: one CTA (256 threads) per (head h, batch b).
// ---------------------------------------------------------------------------
template<int IN_DIM>
__global__ void __launch_bounds__(256, 1)
attn_kernel(const float* __restrict__ x,
            const float* __restrict__ Ew, const float* __restrict__ Eb,
            const float* __restrict__ Kw, const float* __restrict__ Kb,
            const float* __restrict__ Qw, const float* __restrict__ Qb,
            const float* __restrict__ Vw, const float* __restrict__ Vb,
            float* __restrict__ w_out, float* __restrict__ x_out)
{
    extern __shared__ float smem[];
    const int h = blockIdx.x, b = blockIdx.y;
    const int tid = threadIdx.x;

    float* s_x  = smem;                     // 64*IN_DIM (reused as s_w later)
    float* s_se = s_x  + 64 * IN_DIM;       // 64*128
    float* s_kT = s_se + 64 * 128;          // 128*68  (k^T: [e][m])
    float* s_q  = s_kT + 128 * 68;          // 64*128
    float* s_v  = s_q  + 64 * 128;          // 64*32
    float* s_wt = s_v  + 64 * 32;           // 2 * 32*132 staging
    float* s_w  = s_x;                      // 64*64 overlay

    // Load input tile x[b] (coalesced float4); fenced by gemm's first barrier.
    const float* gx = x + (size_t)b * 64 * IN_DIM;
    for (int i = 4 * tid; i < 64 * IN_DIM; i += 1024)
        *(float4*)&s_x[i] = *(const float4*)&gx[i];

    // Phase 1: se = lrelu(x @ Ew^T + Eb)     (8 rows x 4 cols per thread)
    gemm<128, 8>(s_x, IN_DIM, IN_DIM,
                 Ew + (size_t)h * 128 * IN_DIM, Eb + h * 128,
                 s_wt, s_se, 128, false, true, tid);
    // Phase 2: k^T, q (8x4), v (4x2)
    gemm<128, 8>(s_se, 128, 128, Kw + (size_t)h * 128 * 128, Kb + h * 128,
                 s_wt, s_kT, 68, true, false, tid);
    gemm<128, 8>(s_se, 128, 128, Qw + (size_t)h * 128 * 128, Qb + h * 128,
                 s_wt, s_q, 128, false, false, tid);
    gemm<32, 4>(s_se, 128, 128, Vw + (size_t)h * 32 * 128, Vb + h * 32,
                s_wt, s_v, 32, false, true, tid);
    __syncthreads();

    // Phase 3: scores (64x64, K=128) + row softmax.
    // Thread grid 32(tx) x 8(ty): 8 rows x 2 cols. A-loads broadcast, B LDS.64.
    {
        const int tx = tid & 31, ty = tid >> 5;
        ull sacc[8];
#pragma unroll
        for (int i = 0; i < 8; ++i) sacc[i] = 0ull;
#pragma unroll 4
        for (int k4 = 0; k4 < 32; ++k4) {
            float4 a[8];
#pragma unroll
            for (int r = 0; r < 8; ++r)
                a[r] = *(const float4*)&s_q[(8 * ty + r) * 128 + 4 * k4];
#pragma unroll
            for (int q = 0; q < 4; ++q) {
                ull bb = *(const ull*)&s_kT[(4 * k4 + q) * 68 + 2 * tx];
#pragma unroll
                for (int r = 0; r < 8; ++r)
                    sacc[r] = fma2(pack2((&a[r].x)[q], (&a[r].x)[q]), bb, sacc[r]);
            }
        }
        const float SCALE = 0.08838834764831845f;  // 1/sqrt(128)
        float* wg = w_out + (((size_t)h * Bb + b) * 64) * 64;
#pragma unroll
        for (int i = 0; i < 8; ++i) {
            float sc0, sc1; unpack2(sacc[i], sc0, sc1);
            sc0 *= SCALE; sc1 *= SCALE;
            float m = fmaxf(sc0, sc1);
#pragma unroll
            for (int off = 1; off < 32; off <<= 1)
                m = fmaxf(m, __shfl_xor_sync(0xffffffffu, m, off));
            sc0 = __expf(sc0 - m); sc1 = __expf(sc1 - m);
            float s = sc0 + sc1;
#pragma unroll
            for (int off = 1; off < 32; off <<= 1)
                s += __shfl_xor_sync(0xffffffffu, s, off);
            float inv = 1.0f / s;
            float2 wv = make_float2(sc0 * inv, sc1 * inv);
            int row = 8 * ty + i;
            *(float2*)&s_w[row * 64 + 2 * tx] = wv;
            *(float2*)&wg[(size_t)row * 64 + 2 * tx] = wv;
        }
    }
    __syncthreads();

    // Phase 4: att = w @ v (64x32, K=64). Thread grid 16x16: 4 rows x 2 cols.
    {
        const int tx = tid & 15, ty = tid >> 4;
        ull aacc[4] = {0ull, 0ull, 0ull, 0ull};
#pragma unroll 4
        for (int k4 = 0; k4 < 16; ++k4) {
            float4 a0 = *(const float4*)&s_w[(4 * ty + 0) * 64 + 4 * k4];
            float4 a1 = *(const float4*)&s_w[(4 * ty + 1) * 64 + 4 * k4];
            float4 a2 = *(const float4*)&s_w[(4 * ty + 2) * 64 + 4 * k4];
            float4 a3 = *(const float4*)&s_w[(4 * ty + 3) * 64 + 4 * k4];
#pragma unroll
            for (int q = 0; q < 4; ++q) {
                ull bb = *(const ull*)&s_v[(4 * k4 + q) * 32 + 2 * tx];
                aacc[0] = fma2(pack2((&a0.x)[q], (&a0.x)[q]), bb, aacc[0]);
                aacc[1] = fma2(pack2((&a1.x)[q], (&a1.x)[q]), bb, aacc[1]);
                aacc[2] = fma2(pack2((&a2.x)[q], (&a2.x)[q]), bb, aacc[2]);
                aacc[3] = fma2(pack2((&a3.x)[q], (&a3.x)[q]), bb, aacc[3]);
            }
        }
#pragma unroll
        for (int i = 0; i < 4; ++i) {
            float v0, v1; unpack2(aacc[i], v0, v1);
            int row = 4 * ty + i;
            *(float2*)&x_out[((size_t)b * 64 + row) * 128 + h * 32 + 2 * tx] =
                make_float2(v0, v1);
        }
    }
}

// ---------------------------------------------------------------------------
// Final MLP + softmax policy head (~5% of runtime).
// ---------------------------------------------------------------------------
__global__ void __launch_bounds__(256)
mlp_kernel(const float* __restrict__ x,
           const float* __restrict__ F1w, const float* __restrict__ F1b,
           const float* __restrict__ F2w, const float* __restrict__ F2b,
           float* __restrict__ out)
{
    __shared__ float sF1[128 * 65];
    __shared__ float sF2[16 * 64];
    __shared__ float sB1[64];
    __shared__ float sB2[16];
    __shared__ float sx[8][2][128];

    const int tid = threadIdx.x, lane = tid & 31, warp = tid >> 5;

    for (int idx = tid; idx < 64 * 128; idx += 256) {
        int o = idx >> 7, d = idx & 127;
        sF1[d * 65 + o] = F1w[idx];
    }
    for (int idx = tid; idx < 16 * 64; idx += 256) sF2[idx] = F2w[idx];
    if (tid < 64) sB1[tid] = F1b[tid];
    if (tid < 16) sB2[tid] = F2b[tid];
    __syncthreads();

    const int NGRP = (Bb * Nn) / 2;
    for (int g = blockIdx.x * 8 + warp; g < NGRP; g += gridDim.x * 8) {
        int row0 = g * 2;
#pragma unroll
        for (int r = 0; r < 2; ++r)
            *(float4*)&sx[warp][r][lane * 4] =
                *(const float4*)&x[(size_t)(row0 + r) * 128 + lane * 4];
        __syncwarp();

        float h0[2], h1[2];
        h0[0] = h0[1] = sB1[lane];
        h1[0] = h1[1] = sB1[lane + 32];
#pragma unroll 8
        for (int d = 0; d < 128; ++d) {
            float w0 = sF1[d * 65 + lane];
            float w1 = sF1[d * 65 + 32 + lane];
#pragma unroll
            for (int r = 0; r < 2; ++r) {
                float xv = sx[warp][r][d];
                h0[r] = fmaf(xv, w0, h0[r]);
                h1[r] = fmaf(xv, w1, h1[r]);
            }
        }
#pragma unroll
        for (int r = 0; r < 2; ++r) { h0[r] = LRELU(h0[r]); h1[r] = LRELU(h1[r]); }

#pragma unroll
        for (int r = 0; r < 2; ++r) {
            float p[16];
#pragma unroll
            for (int j = 0; j < 16; ++j) {
                float t = fmaf(h0[r], sF2[j * 64 + lane],
                               h1[r] * sF2[j * 64 + 32 + lane]);
#pragma unroll
                for (int off = 16; off > 0; off >>= 1)
                    t += __shfl_xor_sync(0xffffffffu, t, off);
                p[j] = t + sB2[j];
            }
            float m = p[0];
#pragma unroll
            for (int j = 1; j < 16; ++j) m = fmaxf(m, p[j]);
            float s = 0.0f;
#pragma unroll
            for (int j = 0; j < 16; ++j) { p[j] = __expf(p[j] - m); s += p[j]; }
            float inv = 1.0f / s;
            float mine = 0.0f;
#pragma unroll
            for (int j = 0; j < 16; ++j) mine = (lane == j) ? p[j] * inv : mine;
            if (lane < 16) out[(size_t)(row0 + r) * 16 + lane] = mine;
        }
        __syncwarp();
    }
}

// ---------------------------------------------------------------------------
extern "C" void kernel_launch(void* const* d_in, const int* in_sizes, int n_in,
                              void* d_out, int out_size)
{
    const float* states = (const float*)d_in[0];
    const float* E1w = (const float*)d_in[1];  const float* E1b = (const float*)d_in[2];
    const float* K1w = (const float*)d_in[3];  const float* K1b = (const float*)d_in[4];
    const float* Q1w = (const float*)d_in[5];  const float* Q1b = (const float*)d_in[6];
    const float* V1w = (const float*)d_in[7];  const float* V1b = (const float*)d_in[8];
    const float* E2w = (const float*)d_in[9];  const float* E2b = (const float*)d_in[10];
    const float* K2w = (const float*)d_in[11]; const float* K2b = (const float*)d_in[12];
    const float* Q2w = (const float*)d_in[13]; const float* Q2b = (const float*)d_in[14];
    const float* V2w = (const float*)d_in[15]; const float* V2b = (const float*)d_in[16];
    const float* F1w = (const float*)d_in[17]; const float* F1b = (const float*)d_in[18];
    const float* F2w = (const float*)d_in[19]; const float* F2b = (const float*)d_in[20];

    float* out    = (float*)d_out;
    float* policy = out;                                      // [512,64,16]
    float* w1     = out + (size_t)Bb * Nn * FOUT;             // [4,512,64,64]
    float* w2     = w1 + (size_t)Hh * Bb * Nn * Nn;           // [4,512,64,64]

    float* x1p = nullptr; float* x2p = nullptr;
    cudaGetSymbolAddress((void**)&x1p, g_x1);
    cudaGetSymbolAddress((void**)&x2p, g_x2);

    const int SMEM1 = (64*256 + 64*128 + 128*68 + 64*128 + 64*32 + 2*32*132) * 4;
    const int SMEM2 = (64*128 + 64*128 + 128*68 + 64*128 + 64*32 + 2*32*132) * 4;
    cudaFuncSetAttribute(attn_kernel<256>, cudaFuncAttributeMaxDynamicSharedMemorySize, SMEM1);
    cudaFuncSetAttribute(attn_kernel<128>, cudaFuncAttributeMaxDynamicSharedMemorySize, SMEM2);

    dim3 grid(Hh, Bb);
    attn_kernel<256><<<grid, 256, SMEM1>>>(states, E1w, E1b, K1w, K1b,
                                           Q1w, Q1b, V1w, V1b, w1, x1p);
    attn_kernel<128><<<grid, 256, SMEM2>>>(x1p, E2w, E2b, K2w, K2b,
                                           Q2w, Q2b, V2w, V2b, w2, x2p);
    mlp_kernel<<<512, 256>>>(x2p, F1w, F1b, F2w, F2b, policy);
}